// round 2
// baseline (speedup 1.0000x reference)
#include <cuda_runtime.h>
#include <math.h>

#define BB   16
#define NBB  512
#define BSS  128
#define KK   32
#define NBLK (BB * NBB)   /* 8192 (b, nb) blocks */
#define GW   0.3f

/* ---- scratch: per-block statistics (device globals; no allocation) ---- */
__device__ float g_sum_vld_p[NBLK];
__device__ float g_cnt_vld  [NBLK];
__device__ float g_sum_unc_p[NBLK];
__device__ float g_sum_unc_p2[NBLK];
__device__ float g_cnt_unc  [NBLK];
__device__ float g_bce_sum  [NBLK];
__device__ float g_bce_cnt  [NBLK];
__device__ float g_sq       [NBLK];
__device__ float g_qu       [NBLK];

__device__ __forceinline__ float warp_sum(float v) {
    #pragma unroll
    for (int o = 16; o > 0; o >>= 1) v += __shfl_down_sync(0xFFFFFFFFu, v, o);
    return v;
}

/* ================= Pass 1: per-block stats + BCE partials ================= */
__global__ void __launch_bounds__(BSS) pass1_kernel(
    const float* __restrict__ logits,
    const float* __restrict__ targets,
    const int*   __restrict__ sup_mask,
    const int*   __restrict__ ign_mask)
{
    const int blk = blockIdx.x;           // b*NBB + nb
    const int s   = threadIdx.x;          // 0..127
    const int e   = blk * BSS + s;        // linear element index (b*N + nb*BS + s)

    const float x  = logits[e];
    const float t  = targets[e];
    const bool  su = sup_mask[e] != 0;
    const bool  ig = ign_mask[e] != 0;
    const bool  vld = !ig;
    const bool  unc = vld && !su;

    const float p = 1.0f / (1.0f + expf(-x));

    float bce = 0.0f;
    if (su) {
        bce = fmaxf(x, 0.0f) - x * t + log1pf(expf(-fabsf(x)));
    }

    float v0 = vld ? p        : 0.0f;   // sum_vld_p
    float v1 = vld ? 1.0f     : 0.0f;   // cnt_vld
    float v2 = unc ? p        : 0.0f;   // sum_unc_p
    float v3 = unc ? p * p    : 0.0f;   // sum_unc_p2
    float v4 = unc ? 1.0f     : 0.0f;   // cnt_unc
    float v5 = bce;                     // bce partial
    float v6 = su  ? 1.0f     : 0.0f;   // bce count

    v0 = warp_sum(v0); v1 = warp_sum(v1); v2 = warp_sum(v2);
    v3 = warp_sum(v3); v4 = warp_sum(v4); v5 = warp_sum(v5); v6 = warp_sum(v6);

    __shared__ float sh[4][7];
    const int wid = s >> 5, lane = s & 31;
    if (lane == 0) {
        sh[wid][0] = v0; sh[wid][1] = v1; sh[wid][2] = v2;
        sh[wid][3] = v3; sh[wid][4] = v4; sh[wid][5] = v5; sh[wid][6] = v6;
    }
    __syncthreads();
    if (s == 0) {
        float a0 = 0, a1 = 0, a2 = 0, a3 = 0, a4 = 0, a5 = 0, a6 = 0;
        #pragma unroll
        for (int w = 0; w < 4; ++w) {
            a0 += sh[w][0]; a1 += sh[w][1]; a2 += sh[w][2];
            a3 += sh[w][3]; a4 += sh[w][4]; a5 += sh[w][5]; a6 += sh[w][6];
        }
        g_sum_vld_p[blk]  = a0;
        g_cnt_vld[blk]    = a1;
        g_sum_unc_p[blk]  = a2;
        g_sum_unc_p2[blk] = a3;
        g_cnt_unc[blk]    = a4;
        g_bce_sum[blk]    = a5;
        g_bce_cnt[blk]    = a6;
    }
}

/* ======= Pass 2: per query block, gather K neighbor block-sums (1 warp/blk) ======= */
__global__ void __launch_bounds__(256) pass2_kernel(
    const int* __restrict__ kv_indices,     // [B, NB, K]
    const int* __restrict__ kv_num_blocks)  // [B, NB]
{
    const int gid  = blockIdx.x * 8 + (threadIdx.x >> 5);  // b*NBB + qb
    const int lane = threadIdx.x & 31;
    if (gid >= NBLK) return;

    const int b   = gid / NBB;
    const int knb = kv_num_blocks[gid];

    float cv = 0.0f, sp = 0.0f;
    if (lane < knb) {                    // K == 32 == warp width; lane == k
        const int idx = kv_indices[gid * KK + lane];
        const int ng  = b * NBB + idx;
        cv = g_cnt_vld[ng];
        sp = g_sum_vld_p[ng];
    }
    cv = warp_sum(cv);
    sp = warp_sum(sp);

    if (lane == 0) {
        const float cnt   = cv;
        const float nmean = sp / fmaxf(cnt, 1.0f);
        const float qunc  = g_cnt_unc[gid];
        const bool  ok    = (qunc > 0.0f) && (knb > 0) && (cnt > 0.0f);
        float sq = g_sum_unc_p2[gid]
                 - 2.0f * nmean * g_sum_unc_p[gid]
                 + nmean * nmean * qunc;
        g_sq[gid] = ok ? sq   : 0.0f;
        g_qu[gid] = ok ? qunc : 0.0f;
    }
}

/* ================= Pass 3: deterministic final reduction ================= */
__global__ void __launch_bounds__(512) pass3_kernel(float* __restrict__ out)
{
    const int tid  = threadIdx.x;
    const int wid  = tid >> 5;
    const int lane = tid & 31;

    /* --- BCE: sum all 8192 partials, fixed strided order --- */
    float bs = 0.0f, bc = 0.0f;
    for (int i = tid; i < NBLK; i += 512) { bs += g_bce_sum[i]; bc += g_bce_cnt[i]; }
    bs = warp_sum(bs);
    bc = warp_sum(bc);

    __shared__ float shs[16], shc[16];
    __shared__ float bsq[16], bqu[16];
    __shared__ float s_bce;
    if (lane == 0) { shs[wid] = bs; shc[wid] = bc; }
    __syncthreads();
    if (wid == 0) {
        float a = (lane < 16) ? shs[lane] : 0.0f;
        float c = (lane < 16) ? shc[lane] : 0.0f;
        a = warp_sum(a);
        c = warp_sum(c);
        if (lane == 0) s_bce = a / fmaxf(c, 1.0f);
    }
    __syncthreads();

    /* --- graph: warp w handles batch w (B == 16 warps) --- */
    float sq = 0.0f, qu = 0.0f;
    for (int i = lane; i < NBB; i += 32) {
        sq += g_sq[wid * NBB + i];
        qu += g_qu[wid * NBB + i];
    }
    sq = warp_sum(sq);
    qu = warp_sum(qu);
    if (lane == 0) { bsq[wid] = sq; bqu[wid] = qu; }
    __syncthreads();

    if (tid == 0) {
        float acc = 0.0f, nv = 0.0f;
        #pragma unroll
        for (int b = 0; b < BB; ++b) {
            if (bqu[b] > 0.0f) {
                acc += bsq[b] / fmaxf(bqu[b], 1.0f);
                nv  += 1.0f;
            }
        }
        const float lg = acc / fmaxf(nv, 1.0f);
        out[0] = s_bce + GW * lg;
    }
}

extern "C" void kernel_launch(void* const* d_in, const int* in_sizes, int n_in,
                              void* d_out, int out_size)
{
    const float* logits        = (const float*)d_in[0];
    const float* targets       = (const float*)d_in[1];
    const int*   sup_mask      = (const int*)d_in[2];
    const int*   ign_mask      = (const int*)d_in[3];
    const int*   kv_indices    = (const int*)d_in[4];
    const int*   kv_num_blocks = (const int*)d_in[5];
    float* out = (float*)d_out;

    pass1_kernel<<<NBLK, BSS>>>(logits, targets, sup_mask, ign_mask);
    pass2_kernel<<<NBLK / 8, 256>>>(kv_indices, kv_num_blocks);
    pass3_kernel<<<1, 512>>>(out);
}

// round 3
// speedup vs baseline: 1.5225x; 1.5225x over previous
#include <cuda_runtime.h>
#include <math.h>

#define BB   16
#define NBB  512
#define BSS  128
#define KK   32
#define NBLK (BB * NBB)   /* 8192 (b, nb) blocks */
#define GW   0.3f

/* ---- scratch: per-block statistics (device globals; no allocation) ---- */
__device__ float g_sum_vld_p [NBLK];
__device__ float g_cnt_vld   [NBLK];
__device__ float g_sum_unc_p [NBLK];
__device__ float g_sum_unc_p2[NBLK];
__device__ float g_cnt_unc   [NBLK];
__device__ float g_bce_sum   [NBLK];
__device__ float g_bce_cnt   [NBLK];
__device__ float g_sq        [NBLK];
__device__ float g_qu        [NBLK];
__device__ unsigned int g_ctr = 0;

__device__ __forceinline__ float warp_sum(float v) {
    #pragma unroll
    for (int o = 16; o > 0; o >>= 1) v += __shfl_down_sync(0xFFFFFFFFu, v, o);
    return v;
}

/* ============ Pass 1: per-block stats + BCE partials (1 warp / block) ============ */
__global__ void __launch_bounds__(256) pass1_kernel(
    const float4* __restrict__ logits,
    const float4* __restrict__ targets,
    const int4*   __restrict__ sup_mask,
    const int4*   __restrict__ ign_mask)
{
    const int lane = threadIdx.x & 31;
    const int wid  = threadIdx.x >> 5;
    const int blk  = blockIdx.x * 8 + wid;       // (b*NBB + nb), grid = 1024
    const int v    = blk * 32 + lane;            // float4 index: 128 elems / 4

    const float4 x4 = logits[v];
    const float4 t4 = targets[v];
    const int4   s4 = sup_mask[v];
    const int4   i4 = ign_mask[v];

    float sum_vld_p = 0.f, sum_unc_p = 0.f, sum_unc_p2 = 0.f, bce = 0.f, cnts = 0.f;

    const float xs[4] = {x4.x, x4.y, x4.z, x4.w};
    const float ts[4] = {t4.x, t4.y, t4.z, t4.w};
    const int   ss[4] = {s4.x, s4.y, s4.z, s4.w};
    const int   is_[4]= {i4.x, i4.y, i4.z, i4.w};

    #pragma unroll
    for (int j = 0; j < 4; ++j) {
        const float x = xs[j];
        const bool  su = ss[j] != 0;
        const bool  ig = is_[j] != 0;
        const bool  vld = !ig;
        const bool  unc = vld && !su;

        const float p = 1.0f / (1.0f + expf(-x));
        if (vld) { sum_vld_p += p; }
        if (unc) { sum_unc_p += p; sum_unc_p2 += p * p; }
        if (su)  { bce += fmaxf(x, 0.0f) - x * ts[j] + log1pf(expf(-fabsf(x))); }
        /* pack counts: vld + 256*unc + 65536*sup  (max sum 128*65793 < 2^24, exact) */
        cnts += (vld ? 1.0f : 0.0f) + (unc ? 256.0f : 0.0f) + (su ? 65536.0f : 0.0f);
    }

    sum_vld_p  = warp_sum(sum_vld_p);
    sum_unc_p  = warp_sum(sum_unc_p);
    sum_unc_p2 = warp_sum(sum_unc_p2);
    bce        = warp_sum(bce);
    cnts       = warp_sum(cnts);

    if (lane == 0) {
        const int ci = (int)cnts;
        g_sum_vld_p [blk] = sum_vld_p;
        g_cnt_vld   [blk] = (float)(ci & 255);
        g_sum_unc_p [blk] = sum_unc_p;
        g_sum_unc_p2[blk] = sum_unc_p2;
        g_cnt_unc   [blk] = (float)((ci >> 8) & 255);
        g_bce_sum   [blk] = bce;
        g_bce_cnt   [blk] = (float)(ci >> 16);
    }
}

/* ===== Pass 2 (+ fused final reduction): gather K neighbor block-sums ===== */
__global__ void __launch_bounds__(256) pass2_kernel(
    const int* __restrict__ kv_indices,     // [B, NB, K]
    const int* __restrict__ kv_num_blocks,  // [B, NB]
    float* __restrict__ out)
{
    const int lane = threadIdx.x & 31;
    const int wid  = threadIdx.x >> 5;
    const int gid  = blockIdx.x * 8 + wid;       // b*NBB + qb, grid = 1024
    const int b    = gid >> 9;                   // /NBB
    const int knb  = kv_num_blocks[gid];

    float cv = 0.0f, sp = 0.0f;
    if (lane < knb) {                            // K == 32 == warp width
        const int idx = kv_indices[gid * KK + lane];
        const int ng  = (b << 9) + idx;
        cv = g_cnt_vld[ng];
        sp = g_sum_vld_p[ng];
    }
    cv = warp_sum(cv);
    sp = warp_sum(sp);

    if (lane == 0) {
        const float cnt   = cv;
        const float nmean = sp / fmaxf(cnt, 1.0f);
        const float qunc  = g_cnt_unc[gid];
        const bool  ok    = (qunc > 0.0f) && (knb > 0) && (cnt > 0.0f);
        float sq = g_sum_unc_p2[gid]
                 - 2.0f * nmean * g_sum_unc_p[gid]
                 + nmean * nmean * qunc;
        g_sq[gid] = ok ? sq   : 0.0f;
        g_qu[gid] = ok ? qunc : 0.0f;
    }

    /* ---- last-CTA final reduction (deterministic fixed-order sums) ---- */
    __shared__ bool is_last;
    __threadfence();
    __syncthreads();
    if (threadIdx.x == 0) {
        const unsigned old = atomicAdd(&g_ctr, 1u);
        is_last = (old == gridDim.x - 1);
    }
    __syncthreads();
    if (!is_last) return;

    /* BCE sums: strided over 8192 partials */
    float bs = 0.0f, bc = 0.0f;
    for (int i = threadIdx.x; i < NBLK; i += 256) { bs += g_bce_sum[i]; bc += g_bce_cnt[i]; }
    bs = warp_sum(bs);
    bc = warp_sum(bc);

    __shared__ float shs[8], shc[8], bsq[BB], bqu[BB];
    if (lane == 0) { shs[wid] = bs; shc[wid] = bc; }

    /* graph: warp w handles batches 2w, 2w+1 */
    #pragma unroll
    for (int t = 0; t < 2; ++t) {
        const int bb = wid * 2 + t;
        float sq = 0.0f, qu = 0.0f;
        for (int i = lane; i < NBB; i += 32) {
            sq += g_sq[bb * NBB + i];
            qu += g_qu[bb * NBB + i];
        }
        sq = warp_sum(sq);
        qu = warp_sum(qu);
        if (lane == 0) { bsq[bb] = sq; bqu[bb] = qu; }
    }
    __syncthreads();

    if (threadIdx.x == 0) {
        float a = 0.0f, c = 0.0f;
        #pragma unroll
        for (int w = 0; w < 8; ++w) { a += shs[w]; c += shc[w]; }
        const float bce = a / fmaxf(c, 1.0f);

        float acc = 0.0f, nv = 0.0f;
        #pragma unroll
        for (int b2 = 0; b2 < BB; ++b2) {
            if (bqu[b2] > 0.0f) {
                acc += bsq[b2] / fmaxf(bqu[b2], 1.0f);
                nv  += 1.0f;
            }
        }
        out[0] = bce + GW * (acc / fmaxf(nv, 1.0f));
        g_ctr = 0;   /* self-reset for next graph replay */
    }
}

extern "C" void kernel_launch(void* const* d_in, const int* in_sizes, int n_in,
                              void* d_out, int out_size)
{
    const float4* logits        = (const float4*)d_in[0];
    const float4* targets       = (const float4*)d_in[1];
    const int4*   sup_mask      = (const int4*)d_in[2];
    const int4*   ign_mask      = (const int4*)d_in[3];
    const int*    kv_indices    = (const int*)d_in[4];
    const int*    kv_num_blocks = (const int*)d_in[5];
    float* out = (float*)d_out;

    pass1_kernel<<<NBLK / 8, 256>>>(logits, targets, sup_mask, ign_mask);
    pass2_kernel<<<NBLK / 8, 256>>>(kv_indices, kv_num_blocks, out);
}